// round 16
// baseline (speedup 1.0000x reference)
#include <cuda_runtime.h>
#include <cuda_fp16.h>
#include <math.h>

// ---------------- global scratch (allocation-free rule) ----------------
static __device__ float2 g_p1[4096 * 845];   // L1 pooled output as {silu, t}
static __device__ float2 g_p2[4096 * 405];   // L2 output as {silu, t}
static __device__ float  g_h[4096 * 98];     // L3 conv output (flattened)
static __device__ float  g_fwT[98 * 200];    // fc_w transposed: [k][o]
static __device__ uint2  g_c2h[625 * 11];    // layer-2 coefs fp16 {c0,c1|c2,c3}, row=o*125+f

__device__ __forceinline__ float silu_f(float x) {
    return __fdividef(x, 1.0f + __expf(-x));
}
__device__ __forceinline__ float tmap(float x) { return (x + 1.0f) * 2.5f + 3.0f; }
__device__ __forceinline__ float cubic4(float4 q, float u) {
    return ((q.w * u + q.z) * u + q.y) * u + q.x;
}
__device__ __forceinline__ float cubic_h(uint2 q, float u) {
    float2 c01 = __half22float2(*reinterpret_cast<const __half2*>(&q.x));
    float2 c23 = __half22float2(*reinterpret_cast<const __half2*>(&q.y));
    return ((c23.y * u + c23.x) * u + c01.y) * u + c01.x;
}

__device__ __forceinline__ float4 coef_from_w(const float* __restrict__ ws, int row, int j) {
    float w[4];
#pragma unroll
    for (int k = 0; k < 4; k++) {
        int g = j - 3 + k;
        w[k] = (g >= 0 && g <= 7) ? __ldg(&ws[row * 8 + g]) : 0.0f;
    }
    const float s6 = 1.0f / 6.0f;
    float4 c;
    c.x = (w[0] + 4.0f * w[1] + w[2]) * s6;
    c.y = (w[2] - w[0]) * 0.5f;
    c.z = (w[0] - 2.0f * w[1] + w[2]) * 0.5f;
    c.w = (-w[0] + 3.0f * w[1] - 3.0f * w[2] + w[3]) * s6;
    return c;
}

// ---------------- setup: fp16 layer-2 table + fc_w transpose ----------------
__global__ void build_tables(const float* __restrict__ ws2, const float* __restrict__ fcw) {
    int stride = gridDim.x * blockDim.x;
    int tid = blockIdx.x * blockDim.x + threadIdx.x;
    for (int i = tid; i < 625 * 11; i += stride) {
        float4 q = coef_from_w(ws2, i / 11, i % 11);
        __half2 h01 = __floats2half2_rn(q.x, q.y);
        __half2 h23 = __floats2half2_rn(q.z, q.w);
        uint2 r;
        r.x = *reinterpret_cast<unsigned*>(&h01);
        r.y = *reinterpret_cast<unsigned*>(&h23);
        g_c2h[i] = r;
    }
    for (int i = tid; i < 200 * 98; i += stride) {
        int o = i / 98, k = i % 98;
        g_fwT[k * 200 + o] = fcw[i];
    }
}

// ---------------- Kernel 1: conv3(Cin=1,O=5) + maxpool2, 3 imgs, 256 thr ----------------
// wb hoisted into registers before the task loop (exact; removes ~45 LDS/task).
#define K1_IMGS 3
__global__ void __launch_bounds__(256)
k1_conv_pool(const float* __restrict__ x, const float* __restrict__ wb1,
             const float* __restrict__ ws1, int B) {
    __shared__ __align__(16) float wbTs[9 * 8];
    __shared__ float4 c1s[45 * 11];
    __shared__ float2 px[K1_IMGS * 784];
    int tid = threadIdx.x;
    int b0 = blockIdx.x * K1_IMGS;
    int nimg = min(K1_IMGS, B - b0);

    for (int i = tid; i < 45 * 11; i += 256) c1s[i] = coef_from_w(ws1, i / 11, i % 11);
    if (tid < 72) {
        int f = tid / 8, o = tid % 8;
        wbTs[tid] = (o < 5) ? __ldg(&wb1[o * 9 + f]) : 0.0f;
    }
    for (int i = tid; i < nimg * 784; i += 256) {
        float v = x[b0 * 784 + i];
        px[i] = make_float2(silu_f(v), tmap(v));
    }
    __syncthreads();

    // hoist base weights into registers (task-invariant)
    float4 wbv[9];
    float wb4[9];
#pragma unroll
    for (int f = 0; f < 9; f++) {
        wbv[f] = *reinterpret_cast<const float4*>(&wbTs[f * 8]);
        wb4[f] = wbTs[f * 8 + 4];
    }

    for (int task = tid; task < nimg * 169; task += 256) {
        int li = task / 169, p = task % 169;
        int ph = p / 13, pw = p % 13;

        float s[16], u[16];
        int jj[16];
#pragma unroll
        for (int i = 0; i < 16; i++) {
            int r = i >> 2, c = i & 3;
            float2 st = px[li * 784 + (2 * ph + r) * 28 + 2 * pw + c];
            s[i] = st.x;
            float fj = floorf(st.y);
            jj[i] = (int)fj;
            u[i] = st.y - fj;
        }

        float best[5];
#pragma unroll
        for (int o = 0; o < 5; o++) best[o] = -3.0e38f;

#pragma unroll
        for (int d = 0; d < 4; d++) {
            int dy = d >> 1, dx = d & 1;
            float a0 = 0, a1 = 0, a2 = 0, a3 = 0, a4 = 0;
#pragma unroll
            for (int r = 0; r < 3; r++)
#pragma unroll
            for (int c = 0; c < 3; c++) {
                int f = r * 3 + c;
                int i = (dy + r) * 4 + (dx + c);
                float sv = s[i];
                a0 += sv * wbv[f].x; a1 += sv * wbv[f].y; a2 += sv * wbv[f].z;
                a3 += sv * wbv[f].w; a4 += sv * wb4[f];
                int j = jj[i];
                float uu = u[i];
                if ((unsigned)j <= 10u) {
                    int i0 = f * 11 + j;
                    a0 += cubic4(c1s[i0], uu);
                    a1 += cubic4(c1s[i0 + 99], uu);
                    a2 += cubic4(c1s[i0 + 198], uu);
                    a3 += cubic4(c1s[i0 + 297], uu);
                    a4 += cubic4(c1s[i0 + 396], uu);
                }
            }
            best[0] = fmaxf(best[0], a0); best[1] = fmaxf(best[1], a1);
            best[2] = fmaxf(best[2], a2); best[3] = fmaxf(best[3], a3);
            best[4] = fmaxf(best[4], a4);
        }
#pragma unroll
        for (int o = 0; o < 5; o++) {
            float v = best[o];
            g_p1[(b0 + li) * 845 + o * 169 + p] = make_float2(silu_f(v), tmap(v));
        }
    }
}

// ---------------- Kernel 2: conv5(Cin=5,O=5), fp16 coefs, 6 imgs, 512 thr, 2 blk/SM ----------------
// smem (bytes): wbTs [0,4000) 16-aligned; c2h uint2 [4000,59000); in float2 [59000,99560)
#define K2_IMGS 6
#define K2_SMEM (4000 + 55000 + K2_IMGS * 845 * 8)
__global__ void __launch_bounds__(512, 2)
k2_conv(const float* __restrict__ wb2, int B) {
    extern __shared__ __align__(16) char smraw[];
    float* wbTs = reinterpret_cast<float*>(smraw);             // 1000
    uint2* c2h  = reinterpret_cast<uint2*>(smraw + 4000);      // 6875
    float2* in  = reinterpret_cast<float2*>(smraw + 59000);    // 6*845
    int tid = threadIdx.x;
    int b0 = blockIdx.x * K2_IMGS;
    int nimg = min(K2_IMGS, B - b0);

    for (int i = tid; i < 6875; i += 512) c2h[i] = g_c2h[i];   // coalesced copy
    for (int i = tid; i < 1000; i += 512) {
        int f = i / 8, o = i % 8;
        wbTs[i] = (o < 5) ? __ldg(&wb2[o * 125 + f]) : 0.0f;
    }
    for (int i = tid; i < nimg * 845; i += 512) in[i] = g_p1[b0 * 845 + i];
    __syncthreads();

    int li = tid / 81, pos = tid % 81;
    if (li >= nimg) return;
    int oy = pos / 9, ox = pos % 9;

    float a0 = 0, a1 = 0, a2 = 0, a3 = 0, a4 = 0;
    for (int c = 0; c < 5; c++) {
        const float2* inc = &in[li * 845 + c * 169];
        for (int kh = 0; kh < 5; kh++) {
            const float2* row = &inc[(oy + kh) * 13 + ox];
            int fbase = (c * 5 + kh) * 5;
#pragma unroll
            for (int kw = 0; kw < 5; kw++) {
                int f = fbase + kw;
                float2 st = row[kw];
                float4 wbv = *reinterpret_cast<const float4*>(&wbTs[f * 8]);
                float wb4 = wbTs[f * 8 + 4];
                a0 += st.x * wbv.x; a1 += st.x * wbv.y; a2 += st.x * wbv.z;
                a3 += st.x * wbv.w; a4 += st.x * wb4;
                float fj = floorf(st.y);
                int j = (int)fj;
                float u = st.y - fj;
                if ((unsigned)j <= 10u) {
                    int i0 = f * 11 + j;
                    a0 += cubic_h(c2h[i0], u);
                    a1 += cubic_h(c2h[i0 + 1375], u);
                    a2 += cubic_h(c2h[i0 + 2750], u);
                    a3 += cubic_h(c2h[i0 + 4125], u);
                    a4 += cubic_h(c2h[i0 + 5500], u);
                }
            }
        }
    }
    int b = b0 + li;
    float acc[5] = {a0, a1, a2, a3, a4};
#pragma unroll
    for (int o = 0; o < 5; o++) {
        float v = acc[o];
        g_p2[b * 405 + o * 81 + pos] = make_float2(silu_f(v), tmap(v));
    }
}

// ---------------- Kernel 3: conv3(Cin=5,O=2), 10 imgs, 512 thr -> g_h (fp32) ----------------
#define K3_IMGS 10
#define K3_SMEM (15840 + K3_IMGS * 405 * 8 + 45 * 8)
__global__ void __launch_bounds__(512)
k3_conv(const float* __restrict__ wb3, const float* __restrict__ ws3, int B) {
    extern __shared__ __align__(16) char smraw3[];
    float4* c3s = reinterpret_cast<float4*>(smraw3);             // 990
    float2* in  = reinterpret_cast<float2*>(smraw3 + 15840);     // 10*405
    float2* wbp = reinterpret_cast<float2*>(smraw3 + 15840 + K3_IMGS * 405 * 8); // 45
    int tid = threadIdx.x;
    int b0 = blockIdx.x * K3_IMGS;
    int nimg = min(K3_IMGS, B - b0);

    for (int i = tid; i < 990; i += 512) c3s[i] = coef_from_w(ws3, i / 11, i % 11);
    if (tid < 45) wbp[tid] = make_float2(__ldg(&wb3[tid]), __ldg(&wb3[45 + tid]));
    for (int i = tid; i < nimg * 405; i += 512) in[i] = g_p2[b0 * 405 + i];
    __syncthreads();

    for (int task = tid; task < nimg * 49; task += 512) {
        int li = task / 49, pos = task % 49;
        int oy = pos / 7, ox = pos % 7;
        float a0 = 0, a1 = 0;
        for (int c = 0; c < 5; c++) {
#pragma unroll
            for (int kh = 0; kh < 3; kh++)
#pragma unroll
            for (int kw = 0; kw < 3; kw++) {
                int f = (c * 3 + kh) * 3 + kw;
                float2 st = in[li * 405 + c * 81 + (oy + kh) * 9 + ox + kw];
                float2 wv = wbp[f];
                a0 += st.x * wv.x;
                a1 += st.x * wv.y;
                float fj = floorf(st.y);
                int j = (int)fj;
                float u = st.y - fj;
                if ((unsigned)j <= 10u) {
                    int i0 = f * 11 + j;
                    a0 += cubic4(c3s[i0], u);
                    a1 += cubic4(c3s[i0 + 495], u);
                }
            }
        }
        int b = b0 + li;
        g_h[b * 98 + pos]      = a0;   // flatten order o*49 + pos
        g_h[b * 98 + 49 + pos] = a1;
    }
}

// ---------------- Kernel 4: FC, warp-per-2-images, fwT via LDG ----------------
#define K4_WARPS 16
__global__ void __launch_bounds__(512)
k4_fc(const float* __restrict__ fcb, float* __restrict__ out, int B) {
    __shared__ float hs[K4_WARPS][2][100];
    int tid = threadIdx.x;
    int wid = tid / 32, lane = tid % 32;
    int img0 = (blockIdx.x * K4_WARPS + wid) * 2;
    if (img0 >= B) return;
    bool has1 = (img0 + 1) < B;

    for (int k = lane; k < 98; k += 32) {
        hs[wid][0][k] = g_h[img0 * 98 + k];
        if (has1) hs[wid][1][k] = g_h[(img0 + 1) * 98 + k];
    }
    __syncwarp();

    const float4* fwT4 = reinterpret_cast<const float4*>(g_fwT);
    const float4* fb4  = reinterpret_cast<const float4*>(fcb);
    const float* h0 = hs[wid][0];
    const float* h1 = hs[wid][1];
    float4* o0 = reinterpret_cast<float4*>(out + img0 * 200);
    float4* o1 = reinterpret_cast<float4*>(out + (img0 + 1) * 200);

    // pass 0: outputs 4*lane .. 4*lane+3
    {
        float4 b = __ldg(&fb4[lane]);
        float4 acc0 = b, acc1 = b;
#pragma unroll 7
        for (int k = 0; k < 98; k++) {
            float4 w = __ldg(&fwT4[k * 50 + lane]);
            float v0 = h0[k], v1 = h1[k];
            acc0.x += v0 * w.x; acc0.y += v0 * w.y; acc0.z += v0 * w.z; acc0.w += v0 * w.w;
            acc1.x += v1 * w.x; acc1.y += v1 * w.y; acc1.z += v1 * w.z; acc1.w += v1 * w.w;
        }
        o0[lane] = acc0;
        if (has1) o1[lane] = acc1;
    }
    // pass 1: outputs 128 + 4*lane (lanes 0..17)
    if (lane < 18) {
        float4 b = __ldg(&fb4[32 + lane]);
        float4 acc0 = b, acc1 = b;
#pragma unroll 7
        for (int k = 0; k < 98; k++) {
            float4 w = __ldg(&fwT4[k * 50 + 32 + lane]);
            float v0 = h0[k], v1 = h1[k];
            acc0.x += v0 * w.x; acc0.y += v0 * w.y; acc0.z += v0 * w.z; acc0.w += v0 * w.w;
            acc1.x += v1 * w.x; acc1.y += v1 * w.y; acc1.z += v1 * w.z; acc1.w += v1 * w.w;
        }
        o0[32 + lane] = acc0;
        if (has1) o1[32 + lane] = acc1;
    }
}

extern "C" void kernel_launch(void* const* d_in, const int* in_sizes, int n_in,
                              void* d_out, int out_size) {
    const float* x   = (const float*)d_in[0];
    const float* wb1 = (const float*)d_in[1];
    const float* ws1 = (const float*)d_in[2];
    const float* wb2 = (const float*)d_in[3];
    const float* ws2 = (const float*)d_in[4];
    const float* wb3 = (const float*)d_in[5];
    const float* ws3 = (const float*)d_in[6];
    const float* fcw = (const float*)d_in[7];
    const float* fcb = (const float*)d_in[8];
    float* out = (float*)d_out;

    int B = in_sizes[0] / 784;

    cudaFuncSetAttribute(k2_conv, cudaFuncAttributeMaxDynamicSharedMemorySize, K2_SMEM);
    cudaFuncSetAttribute(k2_conv, cudaFuncAttributePreferredSharedMemoryCarveout, 100);
    cudaFuncSetAttribute(k3_conv, cudaFuncAttributeMaxDynamicSharedMemorySize, K3_SMEM);

    build_tables<<<40, 512>>>(ws2, fcw);
    k1_conv_pool<<<(B + K1_IMGS - 1) / K1_IMGS, 256>>>(x, wb1, ws1, B);
    k2_conv<<<(B + K2_IMGS - 1) / K2_IMGS, 512, K2_SMEM>>>(wb2, B);
    k3_conv<<<(B + K3_IMGS - 1) / K3_IMGS, 512, K3_SMEM>>>(wb3, ws3, B);
    k4_fc<<<(B + 2 * K4_WARPS - 1) / (2 * K4_WARPS), 512>>>(fcb, out, B);
}

// round 17
// speedup vs baseline: 1.0909x; 1.0909x over previous
#include <cuda_runtime.h>
#include <cuda_fp16.h>
#include <math.h>

// ---------------- global scratch (allocation-free rule) ----------------
static __device__ float2 g_p1[4096 * 845];   // L1 pooled output as {silu, t}
static __device__ float2 g_p2[4096 * 405];   // L2 output as {silu, t}
static __device__ float  g_h[4096 * 98];     // L3 conv output (flattened)
static __device__ float  g_fwT[98 * 200];    // fc_w transposed: [k][o]
static __device__ uint2  g_c2h[625 * 11];    // layer-2 coefs fp16, row = o*125+f

__device__ __forceinline__ float silu_f(float x) {
    return __fdividef(x, 1.0f + __expf(-x));
}
__device__ __forceinline__ float tmap(float x) { return (x + 1.0f) * 2.5f + 3.0f; }
__device__ __forceinline__ float cubic4(float4 q, float u) {
    return ((q.w * u + q.z) * u + q.y) * u + q.x;
}
// fp16-packed cubic: unpack to fp32, horner in fp32
__device__ __forceinline__ float cubic_h(uint2 q, float u) {
    float2 c01 = __half22float2(*reinterpret_cast<const __half2*>(&q.x));
    float2 c23 = __half22float2(*reinterpret_cast<const __half2*>(&q.y));
    return ((c23.y * u + c23.x) * u + c01.y) * u + c01.x;
}

__device__ __forceinline__ float4 coef_from_w(const float* __restrict__ ws, int row, int j) {
    float w[4];
#pragma unroll
    for (int k = 0; k < 4; k++) {
        int g = j - 3 + k;
        w[k] = (g >= 0 && g <= 7) ? __ldg(&ws[row * 8 + g]) : 0.0f;
    }
    const float s6 = 1.0f / 6.0f;
    float4 c;
    c.x = (w[0] + 4.0f * w[1] + w[2]) * s6;
    c.y = (w[2] - w[0]) * 0.5f;
    c.z = (w[0] - 2.0f * w[1] + w[2]) * 0.5f;
    c.w = (-w[0] + 3.0f * w[1] - 3.0f * w[2] + w[3]) * s6;
    return c;
}
__device__ __forceinline__ uint2 coef_h(const float* __restrict__ ws, int row, int j) {
    float4 q = coef_from_w(ws, row, j);
    __half2 h01 = __floats2half2_rn(q.x, q.y);
    __half2 h23 = __floats2half2_rn(q.z, q.w);
    uint2 r;
    r.x = *reinterpret_cast<unsigned*>(&h01);
    r.y = *reinterpret_cast<unsigned*>(&h23);
    return r;
}

// ---------------- setup: fp16 layer-2 table + fc_w transpose ----------------
__global__ void build_tables(const float* __restrict__ ws2, const float* __restrict__ fcw) {
    int stride = gridDim.x * blockDim.x;
    int tid = blockIdx.x * blockDim.x + threadIdx.x;
    for (int i = tid; i < 625 * 11; i += stride) g_c2h[i] = coef_h(ws2, i / 11, i % 11);
    for (int i = tid; i < 200 * 98; i += stride) {
        int o = i / 98, k = i % 98;
        g_fwT[k * 200 + o] = fcw[i];
    }
}

// ---------------- Kernel 1: conv3(Cin=1,O=5) + maxpool2, 6 imgs, 512 thr, fp16 coefs ----------------
#define K1_IMGS 6
__global__ void __launch_bounds__(512)
k1_conv_pool(const float* __restrict__ x, const float* __restrict__ wb1,
             const float* __restrict__ ws1, int B) {
    __shared__ __align__(16) float wbTs[9 * 8];
    __shared__ uint2 c1h[45 * 11];
    __shared__ float2 px[K1_IMGS * 784];
    int tid = threadIdx.x;
    int b0 = blockIdx.x * K1_IMGS;
    int nimg = min(K1_IMGS, B - b0);

    for (int i = tid; i < 45 * 11; i += 512) c1h[i] = coef_h(ws1, i / 11, i % 11);
    if (tid < 72) {
        int f = tid / 8, o = tid % 8;
        wbTs[tid] = (o < 5) ? __ldg(&wb1[o * 9 + f]) : 0.0f;
    }
    for (int i = tid; i < nimg * 784; i += 512) {
        float v = x[b0 * 784 + i];
        px[i] = make_float2(silu_f(v), tmap(v));
    }
    __syncthreads();

    for (int task = tid; task < nimg * 169; task += 512) {
        int li = task / 169, p = task % 169;
        int ph = p / 13, pw = p % 13;

        float s[16], u[16];
        int jj[16];
#pragma unroll
        for (int i = 0; i < 16; i++) {
            int r = i >> 2, c = i & 3;
            float2 st = px[li * 784 + (2 * ph + r) * 28 + 2 * pw + c];
            s[i] = st.x;
            float fj = floorf(st.y);
            jj[i] = (int)fj;
            u[i] = st.y - fj;
        }

        float best[5];
#pragma unroll
        for (int o = 0; o < 5; o++) best[o] = -3.0e38f;

#pragma unroll
        for (int d = 0; d < 4; d++) {
            int dy = d >> 1, dx = d & 1;
            float a0 = 0, a1 = 0, a2 = 0, a3 = 0, a4 = 0;
#pragma unroll
            for (int r = 0; r < 3; r++)
#pragma unroll
            for (int c = 0; c < 3; c++) {
                int f = r * 3 + c;
                int i = (dy + r) * 4 + (dx + c);
                float sv = s[i];
                float4 wbv = *reinterpret_cast<const float4*>(&wbTs[f * 8]);
                float wb4 = wbTs[f * 8 + 4];
                a0 += sv * wbv.x; a1 += sv * wbv.y; a2 += sv * wbv.z;
                a3 += sv * wbv.w; a4 += sv * wb4;
                int j = jj[i];
                float uu = u[i];
                if ((unsigned)j <= 10u) {
                    int i0 = f * 11 + j;
                    a0 += cubic_h(c1h[i0], uu);
                    a1 += cubic_h(c1h[i0 + 99], uu);
                    a2 += cubic_h(c1h[i0 + 198], uu);
                    a3 += cubic_h(c1h[i0 + 297], uu);
                    a4 += cubic_h(c1h[i0 + 396], uu);
                }
            }
            best[0] = fmaxf(best[0], a0); best[1] = fmaxf(best[1], a1);
            best[2] = fmaxf(best[2], a2); best[3] = fmaxf(best[3], a3);
            best[4] = fmaxf(best[4], a4);
        }
#pragma unroll
        for (int o = 0; o < 5; o++) {
            float v = best[o];
            g_p1[(b0 + li) * 845 + o * 169 + p] = make_float2(silu_f(v), tmap(v));
        }
    }
}

// ---------------- Kernel 2: conv5(Cin=5,O=5), fp16 coefs, 6 imgs, 512 thr, 2 blk/SM ----------------
// smem (bytes): wbTs [0,4000) 16-aligned; c2h uint2 [4000,59000); in float2 [59000,99560)
#define K2_IMGS 6
#define K2_SMEM (4000 + 55000 + K2_IMGS * 845 * 8)
__global__ void __launch_bounds__(512, 2)
k2_conv(const float* __restrict__ wb2, int B) {
    extern __shared__ __align__(16) char smraw[];
    float* wbTs = reinterpret_cast<float*>(smraw);             // 1000
    uint2* c2h  = reinterpret_cast<uint2*>(smraw + 4000);      // 6875
    float2* in  = reinterpret_cast<float2*>(smraw + 59000);    // 6*845
    int tid = threadIdx.x;
    int b0 = blockIdx.x * K2_IMGS;
    int nimg = min(K2_IMGS, B - b0);

    for (int i = tid; i < 6875; i += 512) c2h[i] = g_c2h[i];   // coalesced copy
    for (int i = tid; i < 1000; i += 512) {
        int f = i / 8, o = i % 8;
        wbTs[i] = (o < 5) ? __ldg(&wb2[o * 125 + f]) : 0.0f;
    }
    for (int i = tid; i < nimg * 845; i += 512) in[i] = g_p1[b0 * 845 + i];
    __syncthreads();

    int li = tid / 81, pos = tid % 81;
    if (li >= nimg) return;
    int oy = pos / 9, ox = pos % 9;

    float a0 = 0, a1 = 0, a2 = 0, a3 = 0, a4 = 0;
    for (int c = 0; c < 5; c++) {
        const float2* inc = &in[li * 845 + c * 169];
        for (int kh = 0; kh < 5; kh++) {
            const float2* row = &inc[(oy + kh) * 13 + ox];
            int fbase = (c * 5 + kh) * 5;
#pragma unroll
            for (int kw = 0; kw < 5; kw++) {
                int f = fbase + kw;
                float2 st = row[kw];
                float4 wbv = *reinterpret_cast<const float4*>(&wbTs[f * 8]);
                float wb4 = wbTs[f * 8 + 4];
                a0 += st.x * wbv.x; a1 += st.x * wbv.y; a2 += st.x * wbv.z;
                a3 += st.x * wbv.w; a4 += st.x * wb4;
                float fj = floorf(st.y);
                int j = (int)fj;
                float u = st.y - fj;
                if ((unsigned)j <= 10u) {
                    int i0 = f * 11 + j;
                    a0 += cubic_h(c2h[i0], u);
                    a1 += cubic_h(c2h[i0 + 1375], u);
                    a2 += cubic_h(c2h[i0 + 2750], u);
                    a3 += cubic_h(c2h[i0 + 4125], u);
                    a4 += cubic_h(c2h[i0 + 5500], u);
                }
            }
        }
    }
    int b = b0 + li;
    float acc[5] = {a0, a1, a2, a3, a4};
#pragma unroll
    for (int o = 0; o < 5; o++) {
        float v = acc[o];
        g_p2[b * 405 + o * 81 + pos] = make_float2(silu_f(v), tmap(v));
    }
}

// ---------------- Kernel 3: conv3(Cin=5,O=2), 10 imgs, 512 thr -> g_h (fp32) ----------------
#define K3_IMGS 10
#define K3_SMEM (15840 + K3_IMGS * 405 * 8 + 45 * 8)
__global__ void __launch_bounds__(512)
k3_conv(const float* __restrict__ wb3, const float* __restrict__ ws3, int B) {
    extern __shared__ __align__(16) char smraw3[];
    float4* c3s = reinterpret_cast<float4*>(smraw3);             // 990
    float2* in  = reinterpret_cast<float2*>(smraw3 + 15840);     // 10*405
    float2* wbp = reinterpret_cast<float2*>(smraw3 + 15840 + K3_IMGS * 405 * 8); // 45
    int tid = threadIdx.x;
    int b0 = blockIdx.x * K3_IMGS;
    int nimg = min(K3_IMGS, B - b0);

    for (int i = tid; i < 990; i += 512) c3s[i] = coef_from_w(ws3, i / 11, i % 11);
    if (tid < 45) wbp[tid] = make_float2(__ldg(&wb3[tid]), __ldg(&wb3[45 + tid]));
    for (int i = tid; i < nimg * 405; i += 512) in[i] = g_p2[b0 * 405 + i];
    __syncthreads();

    for (int task = tid; task < nimg * 49; task += 512) {
        int li = task / 49, pos = task % 49;
        int oy = pos / 7, ox = pos % 7;
        float a0 = 0, a1 = 0;
        for (int c = 0; c < 5; c++) {
#pragma unroll
            for (int kh = 0; kh < 3; kh++)
#pragma unroll
            for (int kw = 0; kw < 3; kw++) {
                int f = (c * 3 + kh) * 3 + kw;
                float2 st = in[li * 405 + c * 81 + (oy + kh) * 9 + ox + kw];
                float2 wv = wbp[f];
                a0 += st.x * wv.x;
                a1 += st.x * wv.y;
                float fj = floorf(st.y);
                int j = (int)fj;
                float u = st.y - fj;
                if ((unsigned)j <= 10u) {
                    int i0 = f * 11 + j;
                    a0 += cubic4(c3s[i0], u);
                    a1 += cubic4(c3s[i0 + 495], u);
                }
            }
        }
        int b = b0 + li;
        g_h[b * 98 + pos]      = a0;   // flatten order o*49 + pos
        g_h[b * 98 + 49 + pos] = a1;
    }
}

// ---------------- Kernel 4: FC, warp-per-2-images, fwT via LDG ----------------
#define K4_WARPS 16
__global__ void __launch_bounds__(512)
k4_fc(const float* __restrict__ fcb, float* __restrict__ out, int B) {
    __shared__ float hs[K4_WARPS][2][100];
    int tid = threadIdx.x;
    int wid = tid / 32, lane = tid % 32;
    int img0 = (blockIdx.x * K4_WARPS + wid) * 2;
    if (img0 >= B) return;
    bool has1 = (img0 + 1) < B;

    for (int k = lane; k < 98; k += 32) {
        hs[wid][0][k] = g_h[img0 * 98 + k];
        if (has1) hs[wid][1][k] = g_h[(img0 + 1) * 98 + k];
    }
    __syncwarp();

    const float4* fwT4 = reinterpret_cast<const float4*>(g_fwT);
    const float4* fb4  = reinterpret_cast<const float4*>(fcb);
    const float* h0 = hs[wid][0];
    const float* h1 = hs[wid][1];
    float4* o0 = reinterpret_cast<float4*>(out + img0 * 200);
    float4* o1 = reinterpret_cast<float4*>(out + (img0 + 1) * 200);

    {
        float4 b = __ldg(&fb4[lane]);
        float4 acc0 = b, acc1 = b;
#pragma unroll 7
        for (int k = 0; k < 98; k++) {
            float4 w = __ldg(&fwT4[k * 50 + lane]);
            float v0 = h0[k], v1 = h1[k];
            acc0.x += v0 * w.x; acc0.y += v0 * w.y; acc0.z += v0 * w.z; acc0.w += v0 * w.w;
            acc1.x += v1 * w.x; acc1.y += v1 * w.y; acc1.z += v1 * w.z; acc1.w += v1 * w.w;
        }
        o0[lane] = acc0;
        if (has1) o1[lane] = acc1;
    }
    if (lane < 18) {
        float4 b = __ldg(&fb4[32 + lane]);
        float4 acc0 = b, acc1 = b;
#pragma unroll 7
        for (int k = 0; k < 98; k++) {
            float4 w = __ldg(&fwT4[k * 50 + 32 + lane]);
            float v0 = h0[k], v1 = h1[k];
            acc0.x += v0 * w.x; acc0.y += v0 * w.y; acc0.z += v0 * w.z; acc0.w += v0 * w.w;
            acc1.x += v1 * w.x; acc1.y += v1 * w.y; acc1.z += v1 * w.z; acc1.w += v1 * w.w;
        }
        o0[32 + lane] = acc0;
        if (has1) o1[32 + lane] = acc1;
    }
}

extern "C" void kernel_launch(void* const* d_in, const int* in_sizes, int n_in,
                              void* d_out, int out_size) {
    const float* x   = (const float*)d_in[0];
    const float* wb1 = (const float*)d_in[1];
    const float* ws1 = (const float*)d_in[2];
    const float* wb2 = (const float*)d_in[3];
    const float* ws2 = (const float*)d_in[4];
    const float* wb3 = (const float*)d_in[5];
    const float* ws3 = (const float*)d_in[6];
    const float* fcw = (const float*)d_in[7];
    const float* fcb = (const float*)d_in[8];
    float* out = (float*)d_out;

    int B = in_sizes[0] / 784;

    cudaFuncSetAttribute(k2_conv, cudaFuncAttributeMaxDynamicSharedMemorySize, K2_SMEM);
    cudaFuncSetAttribute(k2_conv, cudaFuncAttributePreferredSharedMemoryCarveout, 100);
    cudaFuncSetAttribute(k3_conv, cudaFuncAttributeMaxDynamicSharedMemorySize, K3_SMEM);

    build_tables<<<40, 512>>>(ws2, fcw);
    k1_conv_pool<<<(B + K1_IMGS - 1) / K1_IMGS, 512>>>(x, wb1, ws1, B);
    k2_conv<<<(B + K2_IMGS - 1) / K2_IMGS, 512, K2_SMEM>>>(wb2, B);
    k3_conv<<<(B + K3_IMGS - 1) / K3_IMGS, 512, K3_SMEM>>>(wb3, ws3, B);
    k4_fc<<<(B + 2 * K4_WARPS - 1) / (2 * K4_WARPS), 512>>>(fcb, out, B);
}